// round 17
// baseline (speedup 1.0000x reference)
#include <cuda_runtime.h>

// KREmbedding: Gaussian-weighted context embedding aggregation.
// context: [B, C] int32, center: [B] int32, W: [V, D] float32 -> out [B, D] float32
// B=8192, C=32, D=512, SIGMA=1.0
//
// Round 17: int8 sketch bound via DOT-PRODUCT IDENTITY (half the ALU).
//   Prepass quantizes W[:, :192] (clip +-3.96875, x32, rn) to int8 and stores
//   per-row norm Nx = sum(q^2). Main computes D = sum(qx*qc) with 12 dp4a per
//   lane (4-lane groups, 8 rows per warp-pass); S = Nx + Nc - 2D is EXACTLY
//   sum((qx-qc)^2) in int32 (|terms| <= 3.1M, no overflow). S > 230*1024 =>
//   (quantization error bound) true d2 > 217 > 208 => expf(-d2/2) == 0.0f
//   exactly in the fp32 reference. Survivor test: 2D >= Nx + Nc - T_Q.
//   Survivors (~0.03%) take the exact fp32 cold path against W.
//   Sketch rows padded to 256B (line-aligned). 2 warps per b, grid 4096
//   (R15 structure — best measured main shape).

#define KB_B 8192
#define KB_C 32
#define KB_D 512
#define KB_V 50000
#define NTHREADS 128            // 4 warps = 2 batch rows per block
#define QSTRIDE 16              // int4 per row (padded; 192B data + 64B pad)
#define T_Q (230 * 1024)
#define T_INT (220 * 1024)
#define ROW_BYTES (KB_D * 4)

__device__ int4 g_q8[KB_V * QSTRIDE];   // 12.8 MB padded int8 sketch
__device__ int  g_norm[KB_V];           // per-row sum of squares (0.2 MB)

// ---------------- prepass: quantize + norm; 4 threads per row ----------------
__device__ __forceinline__ int quant4(float4 v) {
    int q0 = __float2int_rn(fminf(fmaxf(v.x, -3.96875f), 3.96875f) * 32.f);
    int q1 = __float2int_rn(fminf(fmaxf(v.y, -3.96875f), 3.96875f) * 32.f);
    int q2 = __float2int_rn(fminf(fmaxf(v.z, -3.96875f), 3.96875f) * 32.f);
    int q3 = __float2int_rn(fminf(fmaxf(v.w, -3.96875f), 3.96875f) * 32.f);
    return (q0 & 0xFF) | ((q1 & 0xFF) << 8) | ((q2 & 0xFF) << 16) | ((q3 & 0xFF) << 24);
}

__global__ void kre_prep(const float* __restrict__ W)
{
    const int t = blockIdx.x * blockDim.x + threadIdx.x;
    const int row  = t >> 2;                 // 4 threads per row
    const int part = t & 3;                  // 48 elems each
    if (row >= KB_V) return;                 // whole warps exit (200000 % 32 == 0)

    const float4* src = reinterpret_cast<const float4*>(W + (size_t)row * KB_D) + part * 12;
    int q[12];
#pragma unroll
    for (int j = 0; j < 12; j++) q[j] = quant4(__ldg(&src[j]));

    int4* dst = g_q8 + row * QSTRIDE + part * 3;
    dst[0] = make_int4(q[0], q[1], q[2],  q[3]);
    dst[1] = make_int4(q[4], q[5], q[6],  q[7]);
    dst[2] = make_int4(q[8], q[9], q[10], q[11]);

    int n = 0;
#pragma unroll
    for (int j = 0; j < 12; j++) n = __dp4a(q[j], q[j], n);
    n += __shfl_xor_sync(0xffffffffu, n, 2);   // group-of-4 reduce (aligned)
    n += __shfl_xor_sync(0xffffffffu, n, 1);
    if (part == 0) g_norm[row] = n;
}

// ---------------- main kernel ----------------
__device__ __forceinline__ float warp_sum(float v) {
#pragma unroll
    for (int off = 16; off; off >>= 1)
        v += __shfl_xor_sync(0xffffffffu, v, off);
    return v;
}

__device__ __forceinline__ float quarter_d2(float4 r, float4 c) {
    float dx = r.x - c.x, dy = r.y - c.y, dz = r.z - c.z, dw = r.w - c.w;
    float d = dx * dx;
    d = fmaf(dy, dy, d);
    d = fmaf(dz, dz, d);
    d = fmaf(dw, dw, d);
    return d;
}

__device__ __forceinline__ int bound_int(float p) {
    return __float2int_rd(fminf(p, 60000.f) * 1024.f);
}

__device__ __forceinline__ int dp4_dot(int4 x, int4 c, int acc) {
    acc = __dp4a(x.x, c.x, acc);
    acc = __dp4a(x.y, c.y, acc);
    acc = __dp4a(x.z, c.z, acc);
    acc = __dp4a(x.w, c.w, acc);
    return acc;
}

// Cold path: warp-uniform entry, ~0.03% of rows. Exact full fp32 distance
// against W; fixed-point REDUX bound prunes first; lazy acc init.
__device__ __noinline__ float slow_path(const float4* __restrict__ rowp,
                                        const float4* __restrict__ cenp,
                                        int lane,
                                        float4* __restrict__ sacc,
                                        int* __restrict__ flag)
{
    const float4 cen0 = __ldg(&cenp[lane]);
    const float4 cen1 = __ldg(&cenp[lane + 32]);
    const float4 r0   = __ldg(&rowp[lane]);
    const float4 r1   = __ldg(&rowp[lane + 32]);
    const float pa  = quarter_d2(r0, cen0) + quarter_d2(r1, cen1);
    const int s2 = __reduce_add_sync(0xffffffffu, bound_int(pa));
    if (s2 > T_INT) return 0.f;                    // provably w == 0.0f

    if (*flag == 0) {                              // lazy init, warp-private slice
#pragma unroll
        for (int i = 0; i < 4; i++)
            sacc[lane + 32 * i] = make_float4(0.f, 0.f, 0.f, 0.f);
        __syncwarp();
        if (lane == 0) *flag = 1;
    }

    const float4 cen2 = __ldg(&cenp[lane + 64]);
    const float4 cen3 = __ldg(&cenp[lane + 96]);
    const float4 r2   = __ldg(&rowp[lane + 64]);
    const float4 r3   = __ldg(&rowp[lane + 96]);
    const float t  = warp_sum(pa);
    const float d2 = t + warp_sum(quarter_d2(r2, cen2) + quarter_d2(r3, cen3));

    const float e = __expf(-0.5f * d2);

    float4 a;
    a = sacc[lane];
    a.x = fmaf(e, r0.x, a.x); a.y = fmaf(e, r0.y, a.y);
    a.z = fmaf(e, r0.z, a.z); a.w = fmaf(e, r0.w, a.w);
    sacc[lane] = a;
    a = sacc[lane + 32];
    a.x = fmaf(e, r1.x, a.x); a.y = fmaf(e, r1.y, a.y);
    a.z = fmaf(e, r1.z, a.z); a.w = fmaf(e, r1.w, a.w);
    sacc[lane + 32] = a;
    a = sacc[lane + 64];
    a.x = fmaf(e, r2.x, a.x); a.y = fmaf(e, r2.y, a.y);
    a.z = fmaf(e, r2.z, a.z); a.w = fmaf(e, r2.w, a.w);
    sacc[lane + 64] = a;
    a = sacc[lane + 96];
    a.x = fmaf(e, r3.x, a.x); a.y = fmaf(e, r3.y, a.y);
    a.z = fmaf(e, r3.z, a.z); a.w = fmaf(e, r3.w, a.w);
    sacc[lane + 96] = a;
    return e;
}

__global__ __launch_bounds__(NTHREADS, 10)
void kre_kernel(const int* __restrict__ context,
                const int* __restrict__ center,
                const float* __restrict__ W,
                float* __restrict__ out)
{
    const int tid  = threadIdx.x;
    const int lane = tid & 31;
    const int wid  = tid >> 5;
    const int b    = blockIdx.x * 2 + (wid >> 1);  // 2 warps per batch row
    const int half = wid & 1;                      // which 16 context rows
    const int sub  = lane & 3;                     // int4 slot within group
    const int grp  = lane >> 2;                    // 8 groups of 4 lanes

    __shared__ float4 s_acc[4][KB_D / 4];          // per-warp slices (8 KB)
    __shared__ float  s_esum[4];
    __shared__ int    s_flag[4];
    float4* sacc = s_acc[wid];
    if (lane == 0) s_flag[wid] = 0;

    const int cen_idx = __ldg(&center[b]);
    const char* Wb = reinterpret_cast<const char*>(W);
    const float4* cenp = reinterpret_cast<const float4*>(Wb + (unsigned)cen_idx * ROW_BYTES);

    // quantized center: this lane's 48B slice + center norm
    const int4* cq = g_q8 + cen_idx * QSTRIDE;
    int4 cenq[3];
#pragma unroll
    for (int k = 0; k < 3; k++) cenq[k] = __ldg(&cq[sub + 4 * k]);
    const int nc = __ldg(&g_norm[cen_idx]);

    // 16 indices for this half, lanes 0..15 (replicated in 16..31)
    const int my_idx = __ldg(&context[b * KB_C + half * 16 + (lane & 15)]);

    float esum = 0.f;

    // ---- 2 passes x 8 rows: 4-lane-group dot-product bound ----
    unsigned m[2];
#pragma unroll
    for (int p = 0; p < 2; p++) {
        const int idx = __shfl_sync(0xffffffffu, my_idx, 8 * p + grp);
        const int4* rq = g_q8 + idx * QSTRIDE;
        const int nx = __ldg(&g_norm[idx]);        // broadcast within group

        int acc = 0;                               // D = sum(qx*qc)
#pragma unroll
        for (int k = 0; k < 3; k++)
            acc = dp4_dot(__ldg(&rq[sub + 4 * k]), cenq[k], acc);

        // 2-level tree within each 4-lane group: 8 rows reduced at once
        acc += __shfl_xor_sync(0xffffffffu, acc, 2);
        acc += __shfl_xor_sync(0xffffffffu, acc, 1);

        // survivor iff S = nx + nc - 2D <= T_Q
        m[p] = __ballot_sync(0xffffffffu, 2 * acc >= nx + nc - T_Q);
    }

    if ((m[0] | m[1]) != 0) {                      // rare (~0.2% of warps)
#pragma unroll
        for (int p = 0; p < 2; p++) {
#pragma unroll
            for (int g = 0; g < 8; g++) {
                if ((m[p] >> (4 * g)) & 1u) {
                    const int idx = __shfl_sync(0xffffffffu, my_idx, 8 * p + g);
                    const float4* rowp = reinterpret_cast<const float4*>(
                        Wb + (unsigned)idx * ROW_BYTES);
                    esum += slow_path(rowp, cenp, lane, sacc, &s_flag[wid]);
                }
            }
        }
    }

    if (lane == 0) s_esum[wid] = esum;
    __syncthreads();

    // pair combine: warps {0,1} -> b0, warps {2,3} -> b1; 64 lanes per pair
    const int pair  = tid >> 6;
    const int ptid  = tid & 63;
    const int b_out = blockIdx.x * 2 + pair;
    const int f0 = s_flag[pair * 2];
    const int f1 = s_flag[pair * 2 + 1];

    float4* op = reinterpret_cast<float4*>(out + (size_t)b_out * KB_D);

    if ((f0 | f1) == 0) {
        const float4 z = make_float4(0.f, 0.f, 0.f, 0.f);
#pragma unroll
        for (int i = 0; i < 2; i++)
            __stcs(&op[ptid + 64 * i], z);
    } else {
        const float inv = 1.0f / (s_esum[pair * 2] + s_esum[pair * 2 + 1] + 1e-8f);
#pragma unroll
        for (int i = 0; i < 2; i++) {
            const int j = ptid + 64 * i;
            float4 v = make_float4(0.f, 0.f, 0.f, 0.f);
            if (f0) {
                const float4 a0 = s_acc[pair * 2][j];
                v.x += a0.x; v.y += a0.y; v.z += a0.z; v.w += a0.w;
            }
            if (f1) {
                const float4 a1 = s_acc[pair * 2 + 1][j];
                v.x += a1.x; v.y += a1.y; v.z += a1.z; v.w += a1.w;
            }
            v.x *= inv; v.y *= inv; v.z *= inv; v.w *= inv;
            __stcs(&op[j], v);
        }
    }
}

extern "C" void kernel_launch(void* const* d_in, const int* in_sizes, int n_in,
                              void* d_out, int out_size)
{
    const int* context = (const int*)d_in[0];
    const int* center  = (const int*)d_in[1];
    const float* W     = (const float*)d_in[2];
    for (int i = 0; i < n_in; i++) {
        if (in_sizes[i] == KB_B * KB_C)      context = (const int*)d_in[i];
        else if (in_sizes[i] == KB_B)        center  = (const int*)d_in[i];
        else if (in_sizes[i] > KB_B * KB_C)  W       = (const float*)d_in[i];
    }
    float* out = (float*)d_out;

    const int prep_threads = KB_V * 4;               // 200,000 (divisible by 32)
    kre_prep<<<(prep_threads + 255) / 256, 256>>>(W);
    kre_kernel<<<KB_B / 2, NTHREADS>>>(context, center, W, out);
}